// round 12
// baseline (speedup 1.0000x reference)
#include <cuda_runtime.h>
#include <cstdint>

#define NTOT (16*64*256*256)
#define CHW  (64*256*256)
#define HW   (256*256)

__device__ short g_bufA[NTOT];          // pw outputs (int16 acc)
__device__ short g_bufB[NTOT];          // dw1 output (int16 acc)
__device__ unsigned g_maxX;             // float bits of max|x|
__device__ int g_maxA1, g_maxA3;        // int max|acc| of pw1 / pw2 outputs
__device__ int g_mp[64], g_mn[64];      // per-channel max(acc), max(-acc) of dw1 out
__device__ float g_maxY3f;              // pw2 publishes max|y3| for dw2
__device__ float g_swp1, g_swf1, g_swp2, g_swf2;
__device__ unsigned g_wp1[1024];        // packed int8 weights [co][k] (k = ci/4)
__device__ unsigned g_wp2[1024];
__device__ int g_wf1[576];              // depthwise int weights [c][9]
__device__ int g_wf2[576];

__device__ __forceinline__ unsigned prmt(unsigned a, unsigned b, unsigned s) {
    unsigned d;
    asm("prmt.b32 %0,%1,%2,%3;" : "=r"(d) : "r"(a), "r"(b), "r"(s));
    return d;
}
__device__ __forceinline__ unsigned pack4s(int q0, int q1, int q2, int q3) {
    unsigned t, d;
    int z = 0;
    asm("cvt.pack.sat.s8.s32.b32 %0, %1, %2, %3;" : "=r"(t) : "r"(q3), "r"(q2), "r"(z));
    asm("cvt.pack.sat.s8.s32.b32 %0, %1, %2, %3;" : "=r"(d) : "r"(q1), "r"(q0), "r"(t));
    return d;
}
__device__ __forceinline__ unsigned packs16(int a, int b) {
    unsigned d;
    asm("cvt.pack.sat.s16.s32 %0, %1, %2;" : "=r"(d) : "r"(b), "r"(a));
    return d;
}
// warp int8 MMA: D(16x8) += A(16x32) * B(32x8), s8 x s8 -> s32
__device__ __forceinline__ void imma(int* d, const unsigned* a, unsigned b0, unsigned b1) {
    asm volatile(
        "mma.sync.aligned.m16n8k32.row.col.s32.s8.s8.s32 "
        "{%0,%1,%2,%3},{%4,%5,%6,%7},{%8,%9},{%0,%1,%2,%3};"
        : "+r"(d[0]), "+r"(d[1]), "+r"(d[2]), "+r"(d[3])
        : "r"(a[0]), "r"(a[1]), "r"(a[2]), "r"(a[3]), "r"(b0), "r"(b1));
}

// ---------------- prep: zero maxes, quantize all weights (1 block) ----------
__global__ void k_prep(const float* __restrict__ wp1, const float* __restrict__ wf1,
                       const float* __restrict__ wp2, const float* __restrict__ wf2) {
    __shared__ float red[256];
    int tid = threadIdx.x;
    if (tid == 0) { g_maxX = 0u; g_maxA1 = 0; g_maxA3 = 0; }
    if (tid < 64) { g_mp[tid] = 0; g_mn[tid] = 0; }

    float m = 0.f;
    for (int i = tid; i < 4096; i += 256) m = fmaxf(m, fabsf(wp1[i]));
    red[tid] = m; __syncthreads();
    for (int s = 128; s > 0; s >>= 1) { if (tid < s) red[tid] = fmaxf(red[tid], red[tid+s]); __syncthreads(); }
    float s1 = red[0] / 7.0f + 1e-12f;
    __syncthreads();
    for (int i = tid; i < 1024; i += 256) {
        int co = i >> 4, k = i & 15;
        unsigned pk = 0;
        for (int j = 0; j < 4; j++) {
            float w = wp1[co*64 + k*4 + j];
            int q = __float2int_rn(__fdiv_rn(w, s1));
            q = max(-7, min(7, q));
            pk |= (unsigned)(q & 255) << (8*j);
        }
        g_wp1[i] = pk;
    }
    if (tid == 0) g_swp1 = s1;

    m = 0.f;
    for (int i = tid; i < 576; i += 256) m = fmaxf(m, fabsf(wf1[i]));
    red[tid] = m; __syncthreads();
    for (int s = 128; s > 0; s >>= 1) { if (tid < s) red[tid] = fmaxf(red[tid], red[tid+s]); __syncthreads(); }
    float s2 = red[0] / 7.0f + 1e-12f;
    __syncthreads();
    for (int i = tid; i < 576; i += 256) {
        int q = __float2int_rn(__fdiv_rn(wf1[i], s2));
        g_wf1[i] = max(-7, min(7, q));
    }
    if (tid == 0) g_swf1 = s2;

    m = 0.f;
    for (int i = tid; i < 4096; i += 256) m = fmaxf(m, fabsf(wp2[i]));
    red[tid] = m; __syncthreads();
    for (int s = 128; s > 0; s >>= 1) { if (tid < s) red[tid] = fmaxf(red[tid], red[tid+s]); __syncthreads(); }
    float s3 = red[0] / 7.0f + 1e-12f;
    __syncthreads();
    for (int i = tid; i < 1024; i += 256) {
        int co = i >> 4, k = i & 15;
        unsigned pk = 0;
        for (int j = 0; j < 4; j++) {
            float w = wp2[co*64 + k*4 + j];
            int q = __float2int_rn(__fdiv_rn(w, s3));
            q = max(-7, min(7, q));
            pk |= (unsigned)(q & 255) << (8*j);
        }
        g_wp2[i] = pk;
    }
    if (tid == 0) g_swp2 = s3;

    m = 0.f;
    for (int i = tid; i < 576; i += 256) m = fmaxf(m, fabsf(wf2[i]));
    red[tid] = m; __syncthreads();
    for (int s = 128; s > 0; s >>= 1) { if (tid < s) red[tid] = fmaxf(red[tid], red[tid+s]); __syncthreads(); }
    float s4 = red[0] / 7.0f + 1e-12f;
    __syncthreads();
    for (int i = tid; i < 576; i += 256) {
        int q = __float2int_rn(__fdiv_rn(wf2[i], s4));
        g_wf2[i] = max(-7, min(7, q));
    }
    if (tid == 0) g_swf2 = s4;
}

// ---------------- global max|x| ----------------
__global__ void __launch_bounds__(256) k_maxabs(const float4* __restrict__ x) {
    int base = blockIdx.x * 256 + threadIdx.x;
    float m = 0.f;
    #pragma unroll 8
    for (int it = 0; it < 32; it++) {
        float4 v = __ldcs(x + base + it * (2048 * 256));
        m = fmaxf(m, fmaxf(fmaxf(fabsf(v.x), fabsf(v.y)), fmaxf(fabsf(v.z), fabsf(v.w))));
    }
    #pragma unroll
    for (int o = 16; o; o >>= 1) m = fmaxf(m, __shfl_xor_sync(0xffffffffu, m, o));
    if ((threadIdx.x & 31) == 0) atomicMax(&g_maxX, __float_as_uint(m));
}

// ---------------- 1x1 conv: coalesced loader -> smem -> mma.sync int8 ------
// CTA: 256 px x 64 co x 64 ci; warp w: px [w*32, w*32+32), all 64 co.
__global__ void __launch_bounds__(256, 2) k_pw(int which, const float* __restrict__ xf,
                                               const float* __restrict__ alpha) {
    __shared__ __align__(16) unsigned xs[16][257];   // [ci/4][px] quantized bytes
    __shared__ __align__(16) unsigned ws[16][65];    // [ci/4][co]
    __shared__ __align__(16) short obuf[32][272];    // transpose buffer (co-major)
    __shared__ float rpS[64], rnS[64], fred[64];
    __shared__ int sred[8];

    int tid = threadIdx.x;
    int n = blockIdx.y;
    int px0 = blockIdx.x << 8;

    // ---- scale preamble ----
    float s_x = __uint_as_float(g_maxX) / 127.0f + 1e-12f;
    float inv0 = 0.f;
    if (which == 0) {
        inv0 = 1.0f / s_x;
    } else {
        float cmul1 = s_x * g_swp1;
        float s_y1 = ((float)g_maxA1 * cmul1) / 127.0f + 1e-12f;
        float cmul2 = s_y1 * g_swf1;
        if (tid < 64) {
            float a = alpha[tid];
            rnS[tid] = a;
            float mpf = (float)g_mp[tid] * cmul2;
            float mnf = a * ((float)g_mn[tid] * cmul2);
            fred[tid] = fmaxf(mpf, fabsf(mnf));
        }
        __syncthreads();
        if (tid < 32) {
            float mm = fmaxf(fred[tid], fred[tid + 32]);
            #pragma unroll
            for (int o = 16; o; o >>= 1) mm = fmaxf(mm, __shfl_xor_sync(0xffffffffu, mm, o));
            if (tid == 0) { fred[0] = mm; g_maxY3f = mm; }
        }
        __syncthreads();
        float s3 = fred[0] / 127.0f + 1e-12f;
        float inv3 = 1.0f / s3;
        if (tid < 64) {
            float rp = cmul2 * inv3;
            rpS[tid] = rp;
            rnS[tid] = rnS[tid] * rp;
        }
        __syncthreads();
    }

    // ---- coalesced loader: thread = px; quantize 64 ci -> packed bytes
    if (which == 0) {
        const float* xb = xf + (size_t)n * CHW + px0 + tid;
        #pragma unroll
        for (int k = 0; k < 16; k++) {
            int q0 = __float2int_rn(xb[(size_t)(4*k + 0) * HW] * inv0);
            int q1 = __float2int_rn(xb[(size_t)(4*k + 1) * HW] * inv0);
            int q2 = __float2int_rn(xb[(size_t)(4*k + 2) * HW] * inv0);
            int q3 = __float2int_rn(xb[(size_t)(4*k + 3) * HW] * inv0);
            xs[k][tid] = pack4s(q0, q1, q2, q3);
        }
    } else {
        const short* tb = g_bufB + (size_t)n * CHW + px0 + tid;
        #pragma unroll
        for (int k = 0; k < 16; k++) {
            int q[4];
            #pragma unroll
            for (int j = 0; j < 4; j++) {
                int c = 4*k + j;
                int t = (int)tb[(size_t)c * HW];
                float r = (t > 0) ? rpS[c] : rnS[c];
                q[j] = __float2int_rn((float)t * r);
            }
            xs[k][tid] = pack4s(q[0], q[1], q[2], q[3]);
        }
    }
    {
        const unsigned* wq = which ? g_wp2 : g_wp1;
        for (int i = tid; i < 1024; i += 256) ws[i & 15][i >> 4] = wq[i];
    }
    __syncthreads();

    int wid = tid >> 5, lane = tid & 31;
    int g = lane >> 2, tig = lane & 3;
    int pxb = wid << 5;

    int acc[2][8][4];
    #pragma unroll
    for (int m = 0; m < 2; m++)
        #pragma unroll
        for (int n8 = 0; n8 < 8; n8++)
            #pragma unroll
            for (int r = 0; r < 4; r++) acc[m][n8][r] = 0;

    #pragma unroll
    for (int ks = 0; ks < 2; ks++) {
        // A fragments from xs (mapping validated in R10):
        // aw[m][i] = bytes px = pxb + m*16 + g + 8*(i&1), ci word = tig + 4*(i>>1) + 8*ks
        unsigned aw[2][4];
        #pragma unroll
        for (int m = 0; m < 2; m++)
            #pragma unroll
            for (int i = 0; i < 4; i++)
                aw[m][i] = xs[tig + 4*(i >> 1) + 8*ks][pxb + m*16 + g + 8*(i & 1)];
        #pragma unroll
        for (int n8 = 0; n8 < 8; n8++) {
            unsigned b0 = ws[ks*8 + tig][n8*8 + g];
            unsigned b1 = ws[ks*8 + 4 + tig][n8*8 + g];
            imma(acc[0][n8], aw[0], b0, b1);
            imma(acc[1][n8], aw[1], b0, b1);
        }
    }

    // ---- min/max over raw accs
    int mx = -(1 << 30), mn = (1 << 30);
    #pragma unroll
    for (int m = 0; m < 2; m++)
        #pragma unroll
        for (int n8 = 0; n8 < 8; n8++) {
            int* a4 = acc[m][n8];
            mx = max(mx, max(max(a4[0], a4[1]), max(a4[2], a4[3])));
            mn = min(mn, min(min(a4[0], a4[1]), min(a4[2], a4[3])));
        }

    // ---- two-phase transpose epilogue: 32 co per phase
    short* outbase = g_bufA + (size_t)n * CHW + px0;
    #pragma unroll
    for (int ph = 0; ph < 2; ph++) {
        __syncthreads();
        #pragma unroll
        for (int m = 0; m < 2; m++)
            #pragma unroll
            for (int j = 0; j < 4; j++) {
                int n8 = ph*4 + j;
                int col = j*8 + 2*tig;        // local co 0..31
                int pxl = pxb + m*16 + g;
                int* a4 = acc[m][n8];
                obuf[col][pxl]         = (short)max(-32767, min(32767, a4[0]));
                obuf[col + 1][pxl]     = (short)max(-32767, min(32767, a4[1]));
                obuf[col][pxl + 8]     = (short)max(-32767, min(32767, a4[2]));
                obuf[col + 1][pxl + 8] = (short)max(-32767, min(32767, a4[3]));
            }
        __syncthreads();
        {
            int col = tid >> 3;               // 0..31
            int chunk = tid & 7;              // 0..7, 32 px each
            const uint4* src = (const uint4*)&obuf[col][chunk * 32];
            uint4* dst = (uint4*)(outbase + (size_t)(ph*32 + col) * HW + chunk * 32);
            dst[0] = src[0]; dst[1] = src[1]; dst[2] = src[2]; dst[3] = src[3];
        }
    }

    int amax = max(mx, -mn);
    amax = __reduce_max_sync(0xffffffffu, amax);
    if (lane == 0) sred[wid] = amax;
    __syncthreads();
    if (tid == 0) {
        int m2 = sred[0];
        #pragma unroll
        for (int i = 1; i < 8; i++) m2 = max(m2, sred[i]);
        atomicMax(which ? &g_maxA3 : &g_maxA1, m2);
    }
}

// ---------------- depthwise 3x3 via packed-int8 dp4a ------------------------
__global__ void __launch_bounds__(256) k_dw(int which, const float* __restrict__ alpha,
                                            const float* __restrict__ residual,
                                            float* __restrict__ dout) {
    __shared__ int sW[66][66];
    __shared__ int sred[16];

    int tid = threadIdx.x;
    int c = blockIdx.y, n = blockIdx.z;
    int r0 = blockIdx.x << 6;
    size_t poff = ((size_t)n * 64 + c) * HW;
    const short* plane = g_bufA + poff;

    float s_x = __uint_as_float(g_maxX) / 127.0f + 1e-12f;
    float cmulIn, sIn;
    if (which == 0) {
        float cm1 = s_x * g_swp1;
        cmulIn = cm1;
        sIn = ((float)g_maxA1 * cm1) / 127.0f + 1e-12f;
    } else {
        float s3 = g_maxY3f / 127.0f + 1e-12f;
        float cm3 = s3 * g_swp2;
        cmulIn = cm3;
        sIn = ((float)g_maxA3 * cm3) / 127.0f + 1e-12f;
    }
    float rqs = cmulIn * (1.0f / sIn);
    float cmulOut = sIn * (which ? g_swf2 : g_swf1);

    if (tid < 132) sW[tid >> 1][(tid & 1) ? 65 : 0] = 0;

    for (int idx = tid; idx < 66 * 64; idx += 256) {
        int r = idx >> 6, wc = idx & 63;
        int gr = r0 + r - 1;
        int word = 0;
        if (gr >= 0 && gr < 256) {
            short4 v = *(const short4*)(plane + gr * 256 + (wc << 2));
            int q0 = __float2int_rn((float)v.x * rqs);
            int q1 = __float2int_rn((float)v.y * rqs);
            int q2 = __float2int_rn((float)v.z * rqs);
            int q3 = __float2int_rn((float)v.w * rqs);
            word = (int)pack4s(q0, q1, q2, q3);
        }
        sW[r][1 + wc] = word;
    }

    const int* wqp = (which ? g_wf2 : g_wf1) + c * 9;
    int wlo[3], whi[3];
    #pragma unroll
    for (int kr = 0; kr < 3; kr++) {
        int w0 = wqp[3*kr], w1 = wqp[3*kr + 1], w2 = wqp[3*kr + 2];
        wlo[kr] = (w0 & 0xff) | ((w1 & 0xff) << 8) | ((w2 & 0xff) << 16);
        whi[kr] = wlo[kr] << 8;
    }
    float al = which ? alpha[c] : 0.f;
    __syncthreads();

    int g = tid & 63, rq4 = tid >> 6;
    int Rb = rq4 << 4;

    int A0, B0, C0, A1, B1, C1;
    {
        int L = sW[Rb][g], M = sW[Rb][1 + g], Rw = sW[Rb][2 + g];
        A0 = (int)prmt((unsigned)L, (unsigned)M, 0x6543u); B0 = M;
        C0 = (int)prmt((unsigned)M, (unsigned)Rw, 0x4321u);
        L = sW[Rb + 1][g]; M = sW[Rb + 1][1 + g]; Rw = sW[Rb + 1][2 + g];
        A1 = (int)prmt((unsigned)L, (unsigned)M, 0x6543u); B1 = M;
        C1 = (int)prmt((unsigned)M, (unsigned)Rw, 0x4321u);
    }

    if (which == 0) {
        short* oplane = g_bufB + poff;
        int tp = -(1 << 30), tmin = (1 << 30);
        #pragma unroll
        for (int i = 0; i < 16; i++) {
            int row = Rb + i + 2;
            int L = sW[row][g], M = sW[row][1 + g], Rw = sW[row][2 + g];
            int A2 = (int)prmt((unsigned)L, (unsigned)M, 0x6543u), B2 = M;
            int C2 = (int)prmt((unsigned)M, (unsigned)Rw, 0x4321u);
            int a0 = __dp4a(A0, wlo[0], __dp4a(A1, wlo[1], __dp4a(A2, wlo[2], 0)));
            int a1 = __dp4a(A0, whi[0], __dp4a(A1, whi[1], __dp4a(A2, whi[2], 0)));
            int a2 = __dp4a(B0, whi[0], __dp4a(B1, whi[1], __dp4a(B2, whi[2], 0)));
            int a3 = __dp4a(C0, whi[0], __dp4a(C1, whi[1], __dp4a(C2, whi[2], 0)));
            tp = max(tp, max(max(a0, a1), max(a2, a3)));
            tmin = min(tmin, min(min(a0, a1), min(a2, a3)));
            uint2 st;
            st.x = packs16(a0, a1);
            st.y = packs16(a2, a3);
            *(uint2*)(oplane + (r0 + Rb + i) * 256 + (g << 2)) = st;
            A0 = A1; B0 = B1; C0 = C1;
            A1 = A2; B1 = B2; C1 = C2;
        }
        tp = __reduce_max_sync(0xffffffffu, tp);
        int tn = __reduce_max_sync(0xffffffffu, -tmin);
        if ((tid & 31) == 0) { sred[(tid >> 5)*2] = tp; sred[(tid >> 5)*2 + 1] = tn; }
        __syncthreads();
        if (tid == 0) {
            int mp = sred[0], mn = sred[1];
            #pragma unroll
            for (int i2 = 1; i2 < 8; i2++) { mp = max(mp, sred[2*i2]); mn = max(mn, sred[2*i2 + 1]); }
            atomicMax(&g_mp[c], mp);
            atomicMax(&g_mn[c], mn);
        }
    } else {
        float* oplane = dout + poff;
        const float* rplane = residual + poff;
        #pragma unroll
        for (int i = 0; i < 16; i++) {
            int row = Rb + i + 2;
            int L = sW[row][g], M = sW[row][1 + g], Rw = sW[row][2 + g];
            int A2 = (int)prmt((unsigned)L, (unsigned)M, 0x6543u), B2 = M;
            int C2 = (int)prmt((unsigned)M, (unsigned)Rw, 0x4321u);
            int a0 = __dp4a(A0, wlo[0], __dp4a(A1, wlo[1], __dp4a(A2, wlo[2], 0)));
            int a1 = __dp4a(A0, whi[0], __dp4a(A1, whi[1], __dp4a(A2, whi[2], 0)));
            int a2 = __dp4a(B0, whi[0], __dp4a(B1, whi[1], __dp4a(B2, whi[2], 0)));
            int a3 = __dp4a(C0, whi[0], __dp4a(C1, whi[1], __dp4a(C2, whi[2], 0)));
            int off = (r0 + Rb + i) * 256 + (g << 2);
            float4 rv = *(const float4*)(rplane + off);
            float f0 = (float)a0 * cmulOut; f0 = (f0 > 0.f ? f0 : al * f0) + rv.x;
            float f1 = (float)a1 * cmulOut; f1 = (f1 > 0.f ? f1 : al * f1) + rv.y;
            float f2 = (float)a2 * cmulOut; f2 = (f2 > 0.f ? f2 : al * f2) + rv.z;
            float f3 = (float)a3 * cmulOut; f3 = (f3 > 0.f ? f3 : al * f3) + rv.w;
            *(float4*)(oplane + off) = make_float4(f0, f1, f2, f3);
            A0 = A1; B0 = B1; C0 = C1;
            A1 = A2; B1 = B2; C1 = C2;
        }
    }
}

extern "C" void kernel_launch(void* const* d_in, const int* in_sizes, int n_in,
                              void* d_out, int out_size) {
    const float* x   = (const float*)d_in[0];
    const float* wp1 = (const float*)d_in[1];
    const float* wf1 = (const float*)d_in[2];
    const float* wp2 = (const float*)d_in[3];
    const float* wf2 = (const float*)d_in[4];
    const float* a1  = (const float*)d_in[5];
    const float* a2  = (const float*)d_in[6];
    float* out = (float*)d_out;

    k_prep<<<1, 256>>>(wp1, wf1, wp2, wf2);
    k_maxabs<<<2048, 256>>>((const float4*)x);
    k_pw<<<dim3(256, 16), 256>>>(0, x, nullptr);
    k_dw<<<dim3(4, 64, 16), 256>>>(0, nullptr, nullptr, nullptr);
    k_pw<<<dim3(256, 16), 256>>>(1, nullptr, a1);
    k_dw<<<dim3(4, 64, 16), 256>>>(1, a2, x, out);
}

// round 13
// speedup vs baseline: 1.2635x; 1.2635x over previous
#include <cuda_runtime.h>
#include <cstdint>

#define NTOT (16*64*256*256)
#define CHW  (64*256*256)
#define HW   (256*256)

__device__ short g_bufA[NTOT];          // pw outputs (int16 acc)
__device__ short g_bufB[NTOT];          // dw1 output (int16 acc)
__device__ unsigned g_maxX;             // float bits of max|x|
__device__ int g_maxA1, g_maxA3;        // int max|acc| of pw1 / pw2 outputs
__device__ int g_mp[64], g_mn[64];      // per-channel max(acc), max(-acc) of dw1 out
__device__ float g_maxY3f;              // pw2 publishes max|y3| for dw2
__device__ float g_swp1, g_swf1, g_swp2, g_swf2;
__device__ unsigned g_wp1[1024];        // packed int8 weights [co][k] (k = ci/4)
__device__ unsigned g_wp2[1024];
__device__ int g_wf1[576];              // depthwise int weights [c][9]
__device__ int g_wf2[576];

__device__ __forceinline__ unsigned prmt(unsigned a, unsigned b, unsigned s) {
    unsigned d;
    asm("prmt.b32 %0,%1,%2,%3;" : "=r"(d) : "r"(a), "r"(b), "r"(s));
    return d;
}
__device__ __forceinline__ unsigned pack4s(int q0, int q1, int q2, int q3) {
    unsigned t, d;
    int z = 0;
    asm("cvt.pack.sat.s8.s32.b32 %0, %1, %2, %3;" : "=r"(t) : "r"(q3), "r"(q2), "r"(z));
    asm("cvt.pack.sat.s8.s32.b32 %0, %1, %2, %3;" : "=r"(d) : "r"(q1), "r"(q0), "r"(t));
    return d;
}
__device__ __forceinline__ unsigned packs16(int a, int b) {
    unsigned d;
    asm("cvt.pack.sat.s16.s32 %0, %1, %2;" : "=r"(d) : "r"(b), "r"(a));
    return d;
}

// ---------------- prep: zero maxes, quantize all weights (1 block) ----------
__global__ void k_prep(const float* __restrict__ wp1, const float* __restrict__ wf1,
                       const float* __restrict__ wp2, const float* __restrict__ wf2) {
    __shared__ float red[256];
    int tid = threadIdx.x;
    if (tid == 0) { g_maxX = 0u; g_maxA1 = 0; g_maxA3 = 0; }
    if (tid < 64) { g_mp[tid] = 0; g_mn[tid] = 0; }

    float m = 0.f;
    for (int i = tid; i < 4096; i += 256) m = fmaxf(m, fabsf(wp1[i]));
    red[tid] = m; __syncthreads();
    for (int s = 128; s > 0; s >>= 1) { if (tid < s) red[tid] = fmaxf(red[tid], red[tid+s]); __syncthreads(); }
    float s1 = red[0] / 7.0f + 1e-12f;
    __syncthreads();
    for (int i = tid; i < 1024; i += 256) {
        int co = i >> 4, k = i & 15;
        unsigned pk = 0;
        for (int j = 0; j < 4; j++) {
            float w = wp1[co*64 + k*4 + j];
            int q = __float2int_rn(__fdiv_rn(w, s1));
            q = max(-7, min(7, q));
            pk |= (unsigned)(q & 255) << (8*j);
        }
        g_wp1[i] = pk;
    }
    if (tid == 0) g_swp1 = s1;

    m = 0.f;
    for (int i = tid; i < 576; i += 256) m = fmaxf(m, fabsf(wf1[i]));
    red[tid] = m; __syncthreads();
    for (int s = 128; s > 0; s >>= 1) { if (tid < s) red[tid] = fmaxf(red[tid], red[tid+s]); __syncthreads(); }
    float s2 = red[0] / 7.0f + 1e-12f;
    __syncthreads();
    for (int i = tid; i < 576; i += 256) {
        int q = __float2int_rn(__fdiv_rn(wf1[i], s2));
        g_wf1[i] = max(-7, min(7, q));
    }
    if (tid == 0) g_swf1 = s2;

    m = 0.f;
    for (int i = tid; i < 4096; i += 256) m = fmaxf(m, fabsf(wp2[i]));
    red[tid] = m; __syncthreads();
    for (int s = 128; s > 0; s >>= 1) { if (tid < s) red[tid] = fmaxf(red[tid], red[tid+s]); __syncthreads(); }
    float s3 = red[0] / 7.0f + 1e-12f;
    __syncthreads();
    for (int i = tid; i < 1024; i += 256) {
        int co = i >> 4, k = i & 15;
        unsigned pk = 0;
        for (int j = 0; j < 4; j++) {
            float w = wp2[co*64 + k*4 + j];
            int q = __float2int_rn(__fdiv_rn(w, s3));
            q = max(-7, min(7, q));
            pk |= (unsigned)(q & 255) << (8*j);
        }
        g_wp2[i] = pk;
    }
    if (tid == 0) g_swp2 = s3;

    m = 0.f;
    for (int i = tid; i < 576; i += 256) m = fmaxf(m, fabsf(wf2[i]));
    red[tid] = m; __syncthreads();
    for (int s = 128; s > 0; s >>= 1) { if (tid < s) red[tid] = fmaxf(red[tid], red[tid+s]); __syncthreads(); }
    float s4 = red[0] / 7.0f + 1e-12f;
    __syncthreads();
    for (int i = tid; i < 576; i += 256) {
        int q = __float2int_rn(__fdiv_rn(wf2[i], s4));
        g_wf2[i] = max(-7, min(7, q));
    }
    if (tid == 0) g_swf2 = s4;
}

// ---------------- global max|x| (exact 32 iters, streaming loads) ----------
__global__ void __launch_bounds__(256) k_maxabs(const float4* __restrict__ x) {
    int base = blockIdx.x * 256 + threadIdx.x;
    float m = 0.f;
    #pragma unroll 8
    for (int it = 0; it < 32; it++) {
        float4 v = __ldcs(x + base + it * (2048 * 256));
        m = fmaxf(m, fmaxf(fmaxf(fabsf(v.x), fabsf(v.y)), fmaxf(fabsf(v.z), fabsf(v.w))));
    }
    #pragma unroll
    for (int o = 16; o; o >>= 1) m = fmaxf(m, __shfl_xor_sync(0xffffffffu, m, o));
    if ((threadIdx.x & 31) == 0) atomicMax(&g_maxX, __float_as_uint(m));
}

// ---------------- 1x1 conv (dp4a GEMM, int16 acc out, int max tracking) ----
__global__ void __launch_bounds__(256, 2) k_pw(int which, const float* __restrict__ xf,
                                               const float* __restrict__ alpha) {
    __shared__ __align__(16) unsigned xs[16][256];
    __shared__ __align__(16) unsigned ws[16][64];
    __shared__ float rpS[64], rnS[64];
    __shared__ float fred[64];
    __shared__ int sred[16];

    int tid = threadIdx.x;
    int n = blockIdx.y;
    int px0 = blockIdx.x << 8;

    float s_x = __uint_as_float(g_maxX) / 127.0f + 1e-12f;
    float inv0 = 0.f;

    if (which == 0) {
        inv0 = 1.0f / s_x;
    } else {
        float cmul1 = s_x * g_swp1;
        float s_y1 = ((float)g_maxA1 * cmul1) / 127.0f + 1e-12f;
        float cmul2 = s_y1 * g_swf1;
        if (tid < 64) {
            float a = alpha[tid];
            rnS[tid] = a;   // stash alpha temporarily
            float mpf = (float)g_mp[tid] * cmul2;
            float mnf = a * ((float)g_mn[tid] * cmul2);
            fred[tid] = fmaxf(mpf, fabsf(mnf));
        }
        __syncthreads();
        if (tid < 32) {
            float mm = fmaxf(fred[tid], fred[tid + 32]);
            #pragma unroll
            for (int o = 16; o; o >>= 1) mm = fmaxf(mm, __shfl_xor_sync(0xffffffffu, mm, o));
            if (tid == 0) { fred[0] = mm; g_maxY3f = mm; }
        }
        __syncthreads();
        float s3 = fred[0] / 127.0f + 1e-12f;
        float inv3 = 1.0f / s3;
        if (tid < 64) {
            float rp = cmul2 * inv3;
            rpS[tid] = rp;
            rnS[tid] = rnS[tid] * rp;   // alpha * cmul2 * inv3
        }
        __syncthreads();
    }

    // load 256 px x 64 ci, quantize to int8, pack 4 ci per u32
    if (which == 0) {
        const float* xb = xf + (size_t)n * CHW + px0 + tid;
        #pragma unroll
        for (int k = 0; k < 16; k++) {
            int q0 = __float2int_rn(__ldcs(xb + (size_t)(4*k + 0) * HW) * inv0);
            int q1 = __float2int_rn(__ldcs(xb + (size_t)(4*k + 1) * HW) * inv0);
            int q2 = __float2int_rn(__ldcs(xb + (size_t)(4*k + 2) * HW) * inv0);
            int q3 = __float2int_rn(__ldcs(xb + (size_t)(4*k + 3) * HW) * inv0);
            xs[k][tid] = pack4s(q0, q1, q2, q3);
        }
    } else {
        const short* tb = g_bufB + (size_t)n * CHW + px0 + tid;
        #pragma unroll
        for (int k = 0; k < 16; k++) {
            int q[4];
            #pragma unroll
            for (int j = 0; j < 4; j++) {
                int c = 4*k + j;
                int t = (int)__ldcs(tb + (size_t)c * HW);
                float r = (t > 0) ? rpS[c] : rnS[c];
                q[j] = __float2int_rn((float)t * r);
            }
            xs[k][tid] = pack4s(q[0], q[1], q[2], q[3]);
        }
    }
    {
        const unsigned* wq = which ? g_wp2 : g_wp1;
        for (int i = tid; i < 1024; i += 256) ws[i & 15][i >> 4] = wq[i];
    }
    __syncthreads();

    int cg = tid >> 5, pg = tid & 31;
    int co0 = cg << 3, p0 = pg << 3;

    int acc[8][8];
    #pragma unroll
    for (int c = 0; c < 8; c++)
        #pragma unroll
        for (int p = 0; p < 8; p++) acc[c][p] = 0;

    #pragma unroll
    for (int k = 0; k < 16; k++) {
        uint4 x0 = *(const uint4*)&xs[k][p0];
        uint4 x1 = *(const uint4*)&xs[k][p0 + 4];
        uint4 w0 = *(const uint4*)&ws[k][co0];
        uint4 w1 = *(const uint4*)&ws[k][co0 + 4];
        int xv[8] = {(int)x0.x,(int)x0.y,(int)x0.z,(int)x0.w,(int)x1.x,(int)x1.y,(int)x1.z,(int)x1.w};
        int wv[8] = {(int)w0.x,(int)w0.y,(int)w0.z,(int)w0.w,(int)w1.x,(int)w1.y,(int)w1.z,(int)w1.w};
        #pragma unroll
        for (int c = 0; c < 8; c++)
            #pragma unroll
            for (int p = 0; p < 8; p++)
                acc[c][p] = __dp4a(wv[c], xv[p], acc[c][p]);
    }

    // epilogue: saturating s16 pack + raw min/max tracking, streaming stores
    int mx = -(1 << 30), mn = (1 << 30);
    short* out = g_bufA + (size_t)n * CHW + px0 + p0;
    #pragma unroll
    for (int c = 0; c < 8; c++) {
        unsigned pk2[4];
        #pragma unroll
        for (int pp = 0; pp < 4; pp++) {
            int q0 = acc[c][2*pp], q1 = acc[c][2*pp + 1];
            mx = max(mx, max(q0, q1));
            mn = min(mn, min(q0, q1));
            pk2[pp] = packs16(q0, q1);
        }
        __stcs((uint4*)(out + (size_t)(co0 + c) * HW),
               make_uint4(pk2[0], pk2[1], pk2[2], pk2[3]));
    }
    int amax = max(mx, -mn);
    amax = __reduce_max_sync(0xffffffffu, amax);
    if ((tid & 31) == 0) sred[tid >> 5] = amax;
    __syncthreads();
    if (tid == 0) {
        int m = sred[0];
        #pragma unroll
        for (int i = 1; i < 8; i++) m = max(m, sred[i]);
        atomicMax(which ? &g_maxA3 : &g_maxA1, m);
    }
}

// ---------------- depthwise 3x3 via packed-int8 dp4a ------------------------
// Strip: 256 cols x 64 rows per block; thread = 4 cols x 16 rows.
__global__ void __launch_bounds__(256) k_dw(int which, const float* __restrict__ alpha,
                                            const float* __restrict__ residual,
                                            float* __restrict__ dout) {
    __shared__ int sW[66][66];   // [inrow+1][1+wordcol], zero halo words at 0 / 65
    __shared__ int sred[16];

    int tid = threadIdx.x;
    int c = blockIdx.y, n = blockIdx.z;
    int r0 = blockIdx.x << 6;
    size_t poff = ((size_t)n * 64 + c) * HW;
    const short* plane = g_bufA + poff;

    float s_x = __uint_as_float(g_maxX) / 127.0f + 1e-12f;
    float cmulIn, sIn;
    if (which == 0) {
        float cm1 = s_x * g_swp1;
        cmulIn = cm1;
        sIn = ((float)g_maxA1 * cm1) / 127.0f + 1e-12f;
    } else {
        float s3 = g_maxY3f / 127.0f + 1e-12f;
        float cm3 = s3 * g_swp2;
        cmulIn = cm3;
        sIn = ((float)g_maxA3 * cm3) / 127.0f + 1e-12f;
    }
    float rqs = cmulIn * (1.0f / sIn);
    float cmulOut = sIn * (which ? g_swf2 : g_swf1);

    if (tid < 132) sW[tid >> 1][(tid & 1) ? 65 : 0] = 0;

    // loader: 66 rows x 32 uint4 (16B) each; dequant->requant->pack int8
    for (int idx = tid; idx < 66 * 32; idx += 256) {
        int r = idx >> 5, wc4 = idx & 31;
        int gr = r0 + r - 1;
        int w0 = 0, w1 = 0;
        if (gr >= 0 && gr < 256) {
            uint4 v = __ldcs((const uint4*)(plane + gr * 256 + (wc4 << 3)));
            int q0 = __float2int_rn((float)(short)(v.x)          * rqs);
            int q1 = __float2int_rn((float)((int)v.x >> 16)      * rqs);
            int q2 = __float2int_rn((float)(short)(v.y)          * rqs);
            int q3 = __float2int_rn((float)((int)v.y >> 16)      * rqs);
            int q4 = __float2int_rn((float)(short)(v.z)          * rqs);
            int q5 = __float2int_rn((float)((int)v.z >> 16)      * rqs);
            int q6 = __float2int_rn((float)(short)(v.w)          * rqs);
            int q7 = __float2int_rn((float)((int)v.w >> 16)      * rqs);
            w0 = (int)pack4s(q0, q1, q2, q3);
            w1 = (int)pack4s(q4, q5, q6, q7);
        }
        sW[r][1 + 2*wc4] = w0;
        sW[r][2 + 2*wc4] = w1;
    }

    const int* wqp = (which ? g_wf2 : g_wf1) + c * 9;
    int wlo[3], whi[3];
    #pragma unroll
    for (int kr = 0; kr < 3; kr++) {
        int w0 = wqp[3*kr], w1 = wqp[3*kr + 1], w2 = wqp[3*kr + 2];
        wlo[kr] = (w0 & 0xff) | ((w1 & 0xff) << 8) | ((w2 & 0xff) << 16);
        whi[kr] = wlo[kr] << 8;
    }
    float al = which ? alpha[c] : 0.f;
    __syncthreads();

    int g = tid & 63, rq4 = tid >> 6;
    int Rb = rq4 << 4;

    int A0, B0, C0, A1, B1, C1;
    {
        int L = sW[Rb][g], M = sW[Rb][1 + g], Rw = sW[Rb][2 + g];
        A0 = (int)prmt((unsigned)L, (unsigned)M, 0x6543u); B0 = M;
        C0 = (int)prmt((unsigned)M, (unsigned)Rw, 0x4321u);
        L = sW[Rb + 1][g]; M = sW[Rb + 1][1 + g]; Rw = sW[Rb + 1][2 + g];
        A1 = (int)prmt((unsigned)L, (unsigned)M, 0x6543u); B1 = M;
        C1 = (int)prmt((unsigned)M, (unsigned)Rw, 0x4321u);
    }

    if (which == 0) {
        short* oplane = g_bufB + poff;
        int tp = -(1 << 30), tmin = (1 << 30);
        #pragma unroll
        for (int i = 0; i < 16; i++) {
            int row = Rb + i + 2;
            int L = sW[row][g], M = sW[row][1 + g], Rw = sW[row][2 + g];
            int A2 = (int)prmt((unsigned)L, (unsigned)M, 0x6543u), B2 = M;
            int C2 = (int)prmt((unsigned)M, (unsigned)Rw, 0x4321u);
            int a0 = __dp4a(A0, wlo[0], __dp4a(A1, wlo[1], __dp4a(A2, wlo[2], 0)));
            int a1 = __dp4a(A0, whi[0], __dp4a(A1, whi[1], __dp4a(A2, whi[2], 0)));
            int a2 = __dp4a(B0, whi[0], __dp4a(B1, whi[1], __dp4a(B2, whi[2], 0)));
            int a3 = __dp4a(C0, whi[0], __dp4a(C1, whi[1], __dp4a(C2, whi[2], 0)));
            tp = max(tp, max(max(a0, a1), max(a2, a3)));
            tmin = min(tmin, min(min(a0, a1), min(a2, a3)));
            uint2 st;
            st.x = packs16(a0, a1);
            st.y = packs16(a2, a3);
            __stcs((uint2*)(oplane + (r0 + Rb + i) * 256 + (g << 2)), st);
            A0 = A1; B0 = B1; C0 = C1;
            A1 = A2; B1 = B2; C1 = C2;
        }
        tp = __reduce_max_sync(0xffffffffu, tp);
        int tn = __reduce_max_sync(0xffffffffu, -tmin);
        if ((tid & 31) == 0) { sred[(tid >> 5)*2] = tp; sred[(tid >> 5)*2 + 1] = tn; }
        __syncthreads();
        if (tid == 0) {
            int mp = sred[0], mn = sred[1];
            #pragma unroll
            for (int i2 = 1; i2 < 8; i2++) { mp = max(mp, sred[2*i2]); mn = max(mn, sred[2*i2 + 1]); }
            atomicMax(&g_mp[c], mp);
            atomicMax(&g_mn[c], mn);
        }
    } else {
        float* oplane = dout + poff;
        const float* rplane = residual + poff;
        #pragma unroll
        for (int i = 0; i < 16; i++) {
            int row = Rb + i + 2;
            int L = sW[row][g], M = sW[row][1 + g], Rw = sW[row][2 + g];
            int A2 = (int)prmt((unsigned)L, (unsigned)M, 0x6543u), B2 = M;
            int C2 = (int)prmt((unsigned)M, (unsigned)Rw, 0x4321u);
            int a0 = __dp4a(A0, wlo[0], __dp4a(A1, wlo[1], __dp4a(A2, wlo[2], 0)));
            int a1 = __dp4a(A0, whi[0], __dp4a(A1, whi[1], __dp4a(A2, whi[2], 0)));
            int a2 = __dp4a(B0, whi[0], __dp4a(B1, whi[1], __dp4a(B2, whi[2], 0)));
            int a3 = __dp4a(C0, whi[0], __dp4a(C1, whi[1], __dp4a(C2, whi[2], 0)));
            int off = (r0 + Rb + i) * 256 + (g << 2);
            float4 rv = __ldcs((const float4*)(rplane + off));
            float f0 = (float)a0 * cmulOut; f0 = (f0 > 0.f ? f0 : al * f0) + rv.x;
            float f1 = (float)a1 * cmulOut; f1 = (f1 > 0.f ? f1 : al * f1) + rv.y;
            float f2 = (float)a2 * cmulOut; f2 = (f2 > 0.f ? f2 : al * f2) + rv.z;
            float f3 = (float)a3 * cmulOut; f3 = (f3 > 0.f ? f3 : al * f3) + rv.w;
            __stcs((float4*)(oplane + off), make_float4(f0, f1, f2, f3));
            A0 = A1; B0 = B1; C0 = C1;
            A1 = A2; B1 = B2; C1 = C2;
        }
    }
}

extern "C" void kernel_launch(void* const* d_in, const int* in_sizes, int n_in,
                              void* d_out, int out_size) {
    const float* x   = (const float*)d_in[0];
    const float* wp1 = (const float*)d_in[1];
    const float* wf1 = (const float*)d_in[2];
    const float* wp2 = (const float*)d_in[3];
    const float* wf2 = (const float*)d_in[4];
    const float* a1  = (const float*)d_in[5];
    const float* a2  = (const float*)d_in[6];
    float* out = (float*)d_out;

    k_prep<<<1, 256>>>(wp1, wf1, wp2, wf2);
    k_maxabs<<<2048, 256>>>((const float4*)x);
    k_pw<<<dim3(256, 16), 256>>>(0, x, nullptr);                  // x    -> bufA (acc1), maxA1
    k_dw<<<dim3(4, 64, 16), 256>>>(0, nullptr, nullptr, nullptr); // bufA -> bufB (acc2), mp/mn
    k_pw<<<dim3(256, 16), 256>>>(1, nullptr, a1);                 // bufB -> bufA (acc3), maxA3, maxY3f
    k_dw<<<dim3(4, 64, 16), 256>>>(1, a2, x, out);                // bufA -> out (+x)
}

// round 14
// speedup vs baseline: 1.3167x; 1.0421x over previous
#include <cuda_runtime.h>
#include <cstdint>

#define NTOT (16*64*256*256)
#define CHW  (64*256*256)
#define HW   (256*256)

__device__ short g_bufA[NTOT];          // pw outputs (int16 acc)
__device__ short g_bufB[NTOT];          // dw1 output (int16 acc)
__device__ unsigned g_maxX;             // float bits of max|x|
__device__ int g_maxA1, g_maxA3;        // int max|acc| of pw1 / pw2 outputs
__device__ int g_mp[64], g_mn[64];      // per-channel max(acc), max(-acc) of dw1 out
__device__ float g_maxY3f;              // pw2 publishes max|y3| for dw2
__device__ float g_swp1, g_swf1, g_swp2, g_swf2;
__device__ unsigned g_wp1[1024];        // packed int8 weights [co][k] (k = ci/4)
__device__ unsigned g_wp2[1024];
__device__ int g_wf1[576];              // depthwise int weights [c][9]
__device__ int g_wf2[576];

__device__ __forceinline__ unsigned prmt(unsigned a, unsigned b, unsigned s) {
    unsigned d;
    asm("prmt.b32 %0,%1,%2,%3;" : "=r"(d) : "r"(a), "r"(b), "r"(s));
    return d;
}
__device__ __forceinline__ unsigned pack4s(int q0, int q1, int q2, int q3) {
    unsigned t, d;
    int z = 0;
    asm("cvt.pack.sat.s8.s32.b32 %0, %1, %2, %3;" : "=r"(t) : "r"(q3), "r"(q2), "r"(z));
    asm("cvt.pack.sat.s8.s32.b32 %0, %1, %2, %3;" : "=r"(d) : "r"(q1), "r"(q0), "r"(t));
    return d;
}
__device__ __forceinline__ unsigned packs16(int a, int b) {
    unsigned d;
    asm("cvt.pack.sat.s16.s32 %0, %1, %2;" : "=r"(d) : "r"(b), "r"(a));
    return d;
}

// ---------------- prep: zero maxes, quantize all weights (1 block) ----------
__global__ void k_prep(const float* __restrict__ wp1, const float* __restrict__ wf1,
                       const float* __restrict__ wp2, const float* __restrict__ wf2) {
    __shared__ float red[256];
    int tid = threadIdx.x;
    if (tid == 0) { g_maxX = 0u; g_maxA1 = 0; g_maxA3 = 0; }
    if (tid < 64) { g_mp[tid] = 0; g_mn[tid] = 0; }

    float m = 0.f;
    for (int i = tid; i < 4096; i += 256) m = fmaxf(m, fabsf(wp1[i]));
    red[tid] = m; __syncthreads();
    for (int s = 128; s > 0; s >>= 1) { if (tid < s) red[tid] = fmaxf(red[tid], red[tid+s]); __syncthreads(); }
    float s1 = red[0] / 7.0f + 1e-12f;
    __syncthreads();
    for (int i = tid; i < 1024; i += 256) {
        int co = i >> 4, k = i & 15;
        unsigned pk = 0;
        for (int j = 0; j < 4; j++) {
            float w = wp1[co*64 + k*4 + j];
            int q = __float2int_rn(__fdiv_rn(w, s1));
            q = max(-7, min(7, q));
            pk |= (unsigned)(q & 255) << (8*j);
        }
        g_wp1[i] = pk;
    }
    if (tid == 0) g_swp1 = s1;

    m = 0.f;
    for (int i = tid; i < 576; i += 256) m = fmaxf(m, fabsf(wf1[i]));
    red[tid] = m; __syncthreads();
    for (int s = 128; s > 0; s >>= 1) { if (tid < s) red[tid] = fmaxf(red[tid], red[tid+s]); __syncthreads(); }
    float s2 = red[0] / 7.0f + 1e-12f;
    __syncthreads();
    for (int i = tid; i < 576; i += 256) {
        int q = __float2int_rn(__fdiv_rn(wf1[i], s2));
        g_wf1[i] = max(-7, min(7, q));
    }
    if (tid == 0) g_swf1 = s2;

    m = 0.f;
    for (int i = tid; i < 4096; i += 256) m = fmaxf(m, fabsf(wp2[i]));
    red[tid] = m; __syncthreads();
    for (int s = 128; s > 0; s >>= 1) { if (tid < s) red[tid] = fmaxf(red[tid], red[tid+s]); __syncthreads(); }
    float s3 = red[0] / 7.0f + 1e-12f;
    __syncthreads();
    for (int i = tid; i < 1024; i += 256) {
        int co = i >> 4, k = i & 15;
        unsigned pk = 0;
        for (int j = 0; j < 4; j++) {
            float w = wp2[co*64 + k*4 + j];
            int q = __float2int_rn(__fdiv_rn(w, s3));
            q = max(-7, min(7, q));
            pk |= (unsigned)(q & 255) << (8*j);
        }
        g_wp2[i] = pk;
    }
    if (tid == 0) g_swp2 = s3;

    m = 0.f;
    for (int i = tid; i < 576; i += 256) m = fmaxf(m, fabsf(wf2[i]));
    red[tid] = m; __syncthreads();
    for (int s = 128; s > 0; s >>= 1) { if (tid < s) red[tid] = fmaxf(red[tid], red[tid+s]); __syncthreads(); }
    float s4 = red[0] / 7.0f + 1e-12f;
    __syncthreads();
    for (int i = tid; i < 576; i += 256) {
        int q = __float2int_rn(__fdiv_rn(wf2[i], s4));
        g_wf2[i] = max(-7, min(7, q));
    }
    if (tid == 0) g_swf2 = s4;
}

// ---------------- global max|x| (exact 32 iters, streaming loads) ----------
__global__ void __launch_bounds__(256) k_maxabs(const float4* __restrict__ x) {
    int base = blockIdx.x * 256 + threadIdx.x;
    float m = 0.f;
    #pragma unroll 8
    for (int it = 0; it < 32; it++) {
        float4 v = __ldcs(x + base + it * (2048 * 256));
        m = fmaxf(m, fmaxf(fmaxf(fabsf(v.x), fabsf(v.y)), fmaxf(fabsf(v.z), fabsf(v.w))));
    }
    #pragma unroll
    for (int o = 16; o; o >>= 1) m = fmaxf(m, __shfl_xor_sync(0xffffffffu, m, o));
    if ((threadIdx.x & 31) == 0) atomicMax(&g_maxX, __float_as_uint(m));
}

// ---------------- 1x1 conv (dp4a GEMM, int16 acc out, int max tracking) ----
__global__ void __launch_bounds__(256, 2) k_pw(int which, const float* __restrict__ xf,
                                               const float* __restrict__ alpha) {
    __shared__ __align__(16) unsigned xs[16][256];
    __shared__ __align__(16) unsigned ws[16][64];
    __shared__ float rpS[64], rnS[64];
    __shared__ float fred[64];
    __shared__ int sred[16];

    int tid = threadIdx.x;
    int n = blockIdx.y;
    int px0 = blockIdx.x << 8;

    float s_x = __uint_as_float(g_maxX) / 127.0f + 1e-12f;
    float inv0 = 0.f;

    if (which == 0) {
        inv0 = 1.0f / s_x;
    } else {
        float cmul1 = s_x * g_swp1;
        float s_y1 = ((float)g_maxA1 * cmul1) / 127.0f + 1e-12f;
        float cmul2 = s_y1 * g_swf1;
        if (tid < 64) {
            float a = alpha[tid];
            rnS[tid] = a;   // stash alpha temporarily
            float mpf = (float)g_mp[tid] * cmul2;
            float mnf = a * ((float)g_mn[tid] * cmul2);
            fred[tid] = fmaxf(mpf, fabsf(mnf));
        }
        __syncthreads();
        if (tid < 32) {
            float mm = fmaxf(fred[tid], fred[tid + 32]);
            #pragma unroll
            for (int o = 16; o; o >>= 1) mm = fmaxf(mm, __shfl_xor_sync(0xffffffffu, mm, o));
            if (tid == 0) { fred[0] = mm; g_maxY3f = mm; }
        }
        __syncthreads();
        float s3 = fred[0] / 127.0f + 1e-12f;
        float inv3 = 1.0f / s3;
        if (tid < 64) {
            float rp = cmul2 * inv3;
            rpS[tid] = rp;
            rnS[tid] = rnS[tid] * rp;   // alpha * cmul2 * inv3
        }
        __syncthreads();
    }

    // vectorized loader: thread = (px-group of 4, ci-chunk of 16)
    // loads float4/short4 along px, transposes 4x4, one STS.128 per word-group
    {
        int p4 = tid & 63, cg = tid >> 6;
        int pxb = p4 << 2;
        if (which == 0) {
            const float* xb = xf + (size_t)n * CHW + px0 + pxb;
            #pragma unroll
            for (int w = 0; w < 4; w++) {
                int k = (cg << 2) + w;
                float4 v0 = __ldcs((const float4*)(xb + (size_t)(4*k + 0) * HW));
                float4 v1 = __ldcs((const float4*)(xb + (size_t)(4*k + 1) * HW));
                float4 v2 = __ldcs((const float4*)(xb + (size_t)(4*k + 2) * HW));
                float4 v3 = __ldcs((const float4*)(xb + (size_t)(4*k + 3) * HW));
                unsigned w0 = pack4s(__float2int_rn(v0.x * inv0), __float2int_rn(v1.x * inv0),
                                     __float2int_rn(v2.x * inv0), __float2int_rn(v3.x * inv0));
                unsigned w1 = pack4s(__float2int_rn(v0.y * inv0), __float2int_rn(v1.y * inv0),
                                     __float2int_rn(v2.y * inv0), __float2int_rn(v3.y * inv0));
                unsigned w2 = pack4s(__float2int_rn(v0.z * inv0), __float2int_rn(v1.z * inv0),
                                     __float2int_rn(v2.z * inv0), __float2int_rn(v3.z * inv0));
                unsigned w3 = pack4s(__float2int_rn(v0.w * inv0), __float2int_rn(v1.w * inv0),
                                     __float2int_rn(v2.w * inv0), __float2int_rn(v3.w * inv0));
                *(uint4*)&xs[k][pxb] = make_uint4(w0, w1, w2, w3);
            }
        } else {
            const short* tb = g_bufB + (size_t)n * CHW + px0 + pxb;
            #pragma unroll
            for (int w = 0; w < 4; w++) {
                int k = (cg << 2) + w;
                short4 v0 = __ldcs((const short4*)(tb + (size_t)(4*k + 0) * HW));
                short4 v1 = __ldcs((const short4*)(tb + (size_t)(4*k + 1) * HW));
                short4 v2 = __ldcs((const short4*)(tb + (size_t)(4*k + 2) * HW));
                short4 v3 = __ldcs((const short4*)(tb + (size_t)(4*k + 3) * HW));
                float r0p = rpS[4*k], r0n = rnS[4*k];
                float r1p = rpS[4*k + 1], r1n = rnS[4*k + 1];
                float r2p = rpS[4*k + 2], r2n = rnS[4*k + 2];
                float r3p = rpS[4*k + 3], r3n = rnS[4*k + 3];
                unsigned wd[4];
                #pragma unroll
                for (int j = 0; j < 4; j++) {
                    int t0 = (j == 0 ? v0.x : j == 1 ? v0.y : j == 2 ? v0.z : v0.w);
                    int t1 = (j == 0 ? v1.x : j == 1 ? v1.y : j == 2 ? v1.z : v1.w);
                    int t2 = (j == 0 ? v2.x : j == 1 ? v2.y : j == 2 ? v2.z : v2.w);
                    int t3 = (j == 0 ? v3.x : j == 1 ? v3.y : j == 2 ? v3.z : v3.w);
                    int q0 = __float2int_rn((float)t0 * ((t0 > 0) ? r0p : r0n));
                    int q1 = __float2int_rn((float)t1 * ((t1 > 0) ? r1p : r1n));
                    int q2 = __float2int_rn((float)t2 * ((t2 > 0) ? r2p : r2n));
                    int q3 = __float2int_rn((float)t3 * ((t3 > 0) ? r3p : r3n));
                    wd[j] = pack4s(q0, q1, q2, q3);
                }
                *(uint4*)&xs[k][pxb] = make_uint4(wd[0], wd[1], wd[2], wd[3]);
            }
        }
    }
    {
        const unsigned* wq = which ? g_wp2 : g_wp1;
        for (int i = tid; i < 1024; i += 256) ws[i & 15][i >> 4] = wq[i];
    }
    __syncthreads();

    int cg = tid >> 5, pg = tid & 31;
    int co0 = cg << 3, p0 = pg << 3;

    int acc[8][8];
    #pragma unroll
    for (int c = 0; c < 8; c++)
        #pragma unroll
        for (int p = 0; p < 8; p++) acc[c][p] = 0;

    #pragma unroll
    for (int k = 0; k < 16; k++) {
        uint4 x0 = *(const uint4*)&xs[k][p0];
        uint4 x1 = *(const uint4*)&xs[k][p0 + 4];
        uint4 w0 = *(const uint4*)&ws[k][co0];
        uint4 w1 = *(const uint4*)&ws[k][co0 + 4];
        int xv[8] = {(int)x0.x,(int)x0.y,(int)x0.z,(int)x0.w,(int)x1.x,(int)x1.y,(int)x1.z,(int)x1.w};
        int wv[8] = {(int)w0.x,(int)w0.y,(int)w0.z,(int)w0.w,(int)w1.x,(int)w1.y,(int)w1.z,(int)w1.w};
        #pragma unroll
        for (int c = 0; c < 8; c++)
            #pragma unroll
            for (int p = 0; p < 8; p++)
                acc[c][p] = __dp4a(wv[c], xv[p], acc[c][p]);
    }

    // epilogue: saturating s16 pack + raw min/max tracking, streaming stores
    int mx = -(1 << 30), mn = (1 << 30);
    short* out = g_bufA + (size_t)n * CHW + px0 + p0;
    #pragma unroll
    for (int c = 0; c < 8; c++) {
        unsigned pk2[4];
        #pragma unroll
        for (int pp = 0; pp < 4; pp++) {
            int q0 = acc[c][2*pp], q1 = acc[c][2*pp + 1];
            mx = max(mx, max(q0, q1));
            mn = min(mn, min(q0, q1));
            pk2[pp] = packs16(q0, q1);
        }
        __stcs((uint4*)(out + (size_t)(co0 + c) * HW),
               make_uint4(pk2[0], pk2[1], pk2[2], pk2[3]));
    }
    int amax = max(mx, -mn);
    amax = __reduce_max_sync(0xffffffffu, amax);
    if ((tid & 31) == 0) sred[tid >> 5] = amax;
    __syncthreads();
    if (tid == 0) {
        int m = sred[0];
        #pragma unroll
        for (int i = 1; i < 8; i++) m = max(m, sred[i]);
        atomicMax(which ? &g_maxA3 : &g_maxA1, m);
    }
}

// ---------------- depthwise 3x3 via packed-int8 dp4a ------------------------
// Strip: 256 cols x 64 rows per block; thread = 4 cols x 16 rows.
__global__ void __launch_bounds__(256) k_dw(int which, const float* __restrict__ alpha,
                                            const float* __restrict__ residual,
                                            float* __restrict__ dout) {
    __shared__ int sW[66][66];   // [inrow+1][1+wordcol], zero halo words at 0 / 65
    __shared__ int sred[16];

    int tid = threadIdx.x;
    int c = blockIdx.y, n = blockIdx.z;
    int r0 = blockIdx.x << 6;
    size_t poff = ((size_t)n * 64 + c) * HW;
    const short* plane = g_bufA + poff;

    float s_x = __uint_as_float(g_maxX) / 127.0f + 1e-12f;
    float cmulIn, sIn;
    if (which == 0) {
        float cm1 = s_x * g_swp1;
        cmulIn = cm1;
        sIn = ((float)g_maxA1 * cm1) / 127.0f + 1e-12f;
    } else {
        float s3 = g_maxY3f / 127.0f + 1e-12f;
        float cm3 = s3 * g_swp2;
        cmulIn = cm3;
        sIn = ((float)g_maxA3 * cm3) / 127.0f + 1e-12f;
    }
    float rqs = cmulIn * (1.0f / sIn);
    float cmulOut = sIn * (which ? g_swf2 : g_swf1);

    if (tid < 132) sW[tid >> 1][(tid & 1) ? 65 : 0] = 0;

    // loader: 66 rows x 32 uint4 (16B) each; dequant->requant->pack int8
    for (int idx = tid; idx < 66 * 32; idx += 256) {
        int r = idx >> 5, wc4 = idx & 31;
        int gr = r0 + r - 1;
        int w0 = 0, w1 = 0;
        if (gr >= 0 && gr < 256) {
            uint4 v = __ldcs((const uint4*)(plane + gr * 256 + (wc4 << 3)));
            int q0 = __float2int_rn((float)(short)(v.x)          * rqs);
            int q1 = __float2int_rn((float)((int)v.x >> 16)      * rqs);
            int q2 = __float2int_rn((float)(short)(v.y)          * rqs);
            int q3 = __float2int_rn((float)((int)v.y >> 16)      * rqs);
            int q4 = __float2int_rn((float)(short)(v.z)          * rqs);
            int q5 = __float2int_rn((float)((int)v.z >> 16)      * rqs);
            int q6 = __float2int_rn((float)(short)(v.w)          * rqs);
            int q7 = __float2int_rn((float)((int)v.w >> 16)      * rqs);
            w0 = (int)pack4s(q0, q1, q2, q3);
            w1 = (int)pack4s(q4, q5, q6, q7);
        }
        sW[r][1 + 2*wc4] = w0;
        sW[r][2 + 2*wc4] = w1;
    }

    const int* wqp = (which ? g_wf2 : g_wf1) + c * 9;
    int wlo[3], whi[3];
    #pragma unroll
    for (int kr = 0; kr < 3; kr++) {
        int w0 = wqp[3*kr], w1 = wqp[3*kr + 1], w2 = wqp[3*kr + 2];
        wlo[kr] = (w0 & 0xff) | ((w1 & 0xff) << 8) | ((w2 & 0xff) << 16);
        whi[kr] = wlo[kr] << 8;
    }
    float al = which ? alpha[c] : 0.f;
    __syncthreads();

    int g = tid & 63, rq4 = tid >> 6;
    int Rb = rq4 << 4;

    int A0, B0, C0, A1, B1, C1;
    {
        int L = sW[Rb][g], M = sW[Rb][1 + g], Rw = sW[Rb][2 + g];
        A0 = (int)prmt((unsigned)L, (unsigned)M, 0x6543u); B0 = M;
        C0 = (int)prmt((unsigned)M, (unsigned)Rw, 0x4321u);
        L = sW[Rb + 1][g]; M = sW[Rb + 1][1 + g]; Rw = sW[Rb + 1][2 + g];
        A1 = (int)prmt((unsigned)L, (unsigned)M, 0x6543u); B1 = M;
        C1 = (int)prmt((unsigned)M, (unsigned)Rw, 0x4321u);
    }

    if (which == 0) {
        short* oplane = g_bufB + poff;
        int tp = -(1 << 30), tmin = (1 << 30);
        #pragma unroll
        for (int i = 0; i < 16; i++) {
            int row = Rb + i + 2;
            int L = sW[row][g], M = sW[row][1 + g], Rw = sW[row][2 + g];
            int A2 = (int)prmt((unsigned)L, (unsigned)M, 0x6543u), B2 = M;
            int C2 = (int)prmt((unsigned)M, (unsigned)Rw, 0x4321u);
            int a0 = __dp4a(A0, wlo[0], __dp4a(A1, wlo[1], __dp4a(A2, wlo[2], 0)));
            int a1 = __dp4a(A0, whi[0], __dp4a(A1, whi[1], __dp4a(A2, whi[2], 0)));
            int a2 = __dp4a(B0, whi[0], __dp4a(B1, whi[1], __dp4a(B2, whi[2], 0)));
            int a3 = __dp4a(C0, whi[0], __dp4a(C1, whi[1], __dp4a(C2, whi[2], 0)));
            tp = max(tp, max(max(a0, a1), max(a2, a3)));
            tmin = min(tmin, min(min(a0, a1), min(a2, a3)));
            uint2 st;
            st.x = packs16(a0, a1);
            st.y = packs16(a2, a3);
            __stcs((uint2*)(oplane + (r0 + Rb + i) * 256 + (g << 2)), st);
            A0 = A1; B0 = B1; C0 = C1;
            A1 = A2; B1 = B2; C1 = C2;
        }
        tp = __reduce_max_sync(0xffffffffu, tp);
        int tn = __reduce_max_sync(0xffffffffu, -tmin);
        if ((tid & 31) == 0) { sred[(tid >> 5)*2] = tp; sred[(tid >> 5)*2 + 1] = tn; }
        __syncthreads();
        if (tid == 0) {
            int mp = sred[0], mn = sred[1];
            #pragma unroll
            for (int i2 = 1; i2 < 8; i2++) { mp = max(mp, sred[2*i2]); mn = max(mn, sred[2*i2 + 1]); }
            atomicMax(&g_mp[c], mp);
            atomicMax(&g_mn[c], mn);
        }
    } else {
        float* oplane = dout + poff;
        const float* rplane = residual + poff;
        #pragma unroll
        for (int i = 0; i < 16; i++) {
            int row = Rb + i + 2;
            int L = sW[row][g], M = sW[row][1 + g], Rw = sW[row][2 + g];
            int A2 = (int)prmt((unsigned)L, (unsigned)M, 0x6543u), B2 = M;
            int C2 = (int)prmt((unsigned)M, (unsigned)Rw, 0x4321u);
            int a0 = __dp4a(A0, wlo[0], __dp4a(A1, wlo[1], __dp4a(A2, wlo[2], 0)));
            int a1 = __dp4a(A0, whi[0], __dp4a(A1, whi[1], __dp4a(A2, whi[2], 0)));
            int a2 = __dp4a(B0, whi[0], __dp4a(B1, whi[1], __dp4a(B2, whi[2], 0)));
            int a3 = __dp4a(C0, whi[0], __dp4a(C1, whi[1], __dp4a(C2, whi[2], 0)));
            int off = (r0 + Rb + i) * 256 + (g << 2);
            float4 rv = __ldcs((const float4*)(rplane + off));
            float f0 = (float)a0 * cmulOut; f0 = (f0 > 0.f ? f0 : al * f0) + rv.x;
            float f1 = (float)a1 * cmulOut; f1 = (f1 > 0.f ? f1 : al * f1) + rv.y;
            float f2 = (float)a2 * cmulOut; f2 = (f2 > 0.f ? f2 : al * f2) + rv.z;
            float f3 = (float)a3 * cmulOut; f3 = (f3 > 0.f ? f3 : al * f3) + rv.w;
            __stcs((float4*)(oplane + off), make_float4(f0, f1, f2, f3));
            A0 = A1; B0 = B1; C0 = C1;
            A1 = A2; B1 = B2; C1 = C2;
        }
    }
}

extern "C" void kernel_launch(void* const* d_in, const int* in_sizes, int n_in,
                              void* d_out, int out_size) {
    const float* x   = (const float*)d_in[0];
    const float* wp1 = (const float*)d_in[1];
    const float* wf1 = (const float*)d_in[2];
    const float* wp2 = (const float*)d_in[3];
    const float* wf2 = (const float*)d_in[4];
    const float* a1  = (const float*)d_in[5];
    const float* a2  = (const float*)d_in[6];
    float* out = (float*)d_out;

    k_prep<<<1, 256>>>(wp1, wf1, wp2, wf2);
    k_maxabs<<<2048, 256>>>((const float4*)x);
    k_pw<<<dim3(256, 16), 256>>>(0, x, nullptr);                  // x    -> bufA (acc1), maxA1
    k_dw<<<dim3(4, 64, 16), 256>>>(0, nullptr, nullptr, nullptr); // bufA -> bufB (acc2), mp/mn
    k_pw<<<dim3(256, 16), 256>>>(1, nullptr, a1);                 // bufB -> bufA (acc3), maxA3, maxY3f
    k_dw<<<dim3(4, 64, 16), 256>>>(1, a2, x, out);                // bufA -> out (+x)
}